// round 2
// baseline (speedup 1.0000x reference)
#include <cuda_runtime.h>
#include <math.h>

#define EE 64
#define SSZ 128
#define FF 640
#define HH 256
#define GG 768          // 3*H
#define LLN 20
#define CC 32
#define BB (EE*SSZ)     // 8192
#define BLM (BB*LLN)    // 163840
#define EPSV 1e-5f

// ---------------- scratch (static __device__, no allocation) ----------------
__device__ float g_x [BB*HH];       // 8 MB
__device__ float g_gi[BB*GG];       // 24 MB
__device__ float g_hs[BLM*HH];      // 160 MB, layout [b][l][h]
__device__ float g_s1[HH], g_o1[HH];
__device__ float g_s2[HH], g_o2[HH];
__device__ float g_s3[HH], g_o3[HH];
__device__ float g_al[3];

// ---------------- prep: fold BN params into scale/offset --------------------
__global__ void prep_kernel(const float* g1,const float* b1,const float* m1,const float* v1,const float* a1,
                            const float* g2,const float* b2,const float* m2,const float* v2,const float* a2,
                            const float* g3,const float* b3,const float* m3,const float* v3,const float* a3)
{
    int i = threadIdx.x;   // 256 threads, H=256
    float s;
    s = g1[i] / sqrtf(v1[i] + EPSV); g_s1[i] = s; g_o1[i] = b1[i] - m1[i]*s;
    s = g2[i] / sqrtf(v2[i] + EPSV); g_s2[i] = s; g_o2[i] = b2[i] - m2[i]*s;
    s = g3[i] / sqrtf(v3[i] + EPSV); g_s3[i] = s; g_o3[i] = b3[i] - m3[i]*s;
    if (i == 0) { g_al[0] = a1[0]; g_al[1] = a2[0]; g_al[2] = a3[0]; }
}

// ---------------- generic tiled fp32 GEMM:  C = epi(A @ W^T + bias) ---------
// MODE 0: bias only ; MODE 1: bias, then BN1+PReLU epilogue
template<int BM,int BN,int BK,int TM,int TN,int MODE>
__global__ __launch_bounds__(256, 2) void gemm_kernel(
    const float* __restrict__ A, const float* __restrict__ W,
    const float* __restrict__ bias, float* __restrict__ Cst,
    int M, int N, int K)
{
    __shared__ float As[BK][BM+4];
    __shared__ float Ws[BK][BN+4];

    const int tid = threadIdx.x;
    const int m0  = blockIdx.y * BM;
    const int n0  = blockIdx.x * BN;
    constexpr int CT = BN / TN;
    const int tr = tid / CT;
    const int tc = tid % CT;
    constexpr int TNh = TN / 2;

    float acc[TM][TN];
#pragma unroll
    for (int i = 0; i < TM; i++)
#pragma unroll
        for (int j = 0; j < TN; j++) acc[i][j] = 0.f;

    constexpr int NF4A = BM*BK/4;
    constexpr int NF4W = BN*BK/4;

    for (int k0 = 0; k0 < K; k0 += BK) {
#pragma unroll
        for (int it = 0; it < (NF4A + 255) / 256; it++) {
            int idx = tid + it * 256;
            if ((NF4A % 256 == 0) || idx < NF4A) {
                int r = idx >> 2, c = idx & 3;
                float4 v = *(const float4*)(A + (size_t)(m0 + r) * K + k0 + c*4);
                As[c*4+0][r] = v.x; As[c*4+1][r] = v.y;
                As[c*4+2][r] = v.z; As[c*4+3][r] = v.w;
            }
        }
#pragma unroll
        for (int it = 0; it < (NF4W + 255) / 256; it++) {
            int idx = tid + it * 256;
            if ((NF4W % 256 == 0) || idx < NF4W) {
                int r = idx >> 2, c = idx & 3;
                float4 v = *(const float4*)(W + (size_t)(n0 + r) * K + k0 + c*4);
                Ws[c*4+0][r] = v.x; Ws[c*4+1][r] = v.y;
                Ws[c*4+2][r] = v.z; Ws[c*4+3][r] = v.w;
            }
        }
        __syncthreads();

#pragma unroll
        for (int k = 0; k < BK; k++) {
            float ra[TM], rb[TN];
            float4 a0 = *(const float4*)&As[k][tr*TM];
            float4 a1 = *(const float4*)&As[k][tr*TM + 4];
            ra[0]=a0.x; ra[1]=a0.y; ra[2]=a0.z; ra[3]=a0.w;
            ra[4]=a1.x; ra[5]=a1.y; ra[6]=a1.z; ra[7]=a1.w;
            float4 b0 = *(const float4*)&Ws[k][tc*4];
            float4 b1 = *(const float4*)&Ws[k][BN/2 + tc*4];
            rb[0]=b0.x; rb[1]=b0.y; rb[2]=b0.z; rb[3]=b0.w;
            rb[4]=b1.x; rb[5]=b1.y; rb[6]=b1.z; rb[7]=b1.w;
#pragma unroll
            for (int i = 0; i < TM; i++)
#pragma unroll
                for (int j = 0; j < TN; j++)
                    acc[i][j] = fmaf(ra[i], rb[j], acc[i][j]);
        }
        __syncthreads();
    }

#pragma unroll
    for (int j = 0; j < TN; j++) {
        int n = n0 + ((j < TNh) ? (tc*TNh + j) : (BN/2 + tc*TNh + (j - TNh)));
        float bsv = bias[n];
        float sc = 1.f, off = 0.f, al = 0.f;
        if (MODE == 1) { sc = g_s1[n]; off = g_o1[n]; al = g_al[0]; }
#pragma unroll
        for (int i = 0; i < TM; i++) {
            int m = m0 + tr*TM + i;
            float v = acc[i][j] + bsv;
            if (MODE == 1) { v = v*sc + off; v = v >= 0.f ? v : al*v; }
            Cst[(size_t)m * N + n] = v;
        }
    }
}

// ---------------- fused persistent GRU ---------------------------------
// Each block owns GBM=32 batch rows for all 20 steps. h lives in smem (k-major),
// W_hh streamed from L2 per gate pass. r,z stay in registers (same thread
// computes matching n-gate element). One kernel launch total.
#define GBM 32
#define WSP 260                      // padded Ws row (bank-conflict relief)
#define GRU_SMEM ((HH*GBM + 16*WSP) * 4)

__global__ __launch_bounds__(256, 2) void gru_fused_kernel(
    const float* __restrict__ Whh, const float* __restrict__ bhh)
{
    extern __shared__ float sm[];
    float* hT = sm;                   // [HH][GBM] k-major h
    float* Ws = sm + HH*GBM;          // [16][WSP]

    const int tid = threadIdx.x;
    const int tr = tid >> 5;          // 0..7  (TM=4 rows)
    const int tc = tid & 31;          // 0..31 (TN=8 cols, split halves)
    const int b0 = blockIdx.x * GBM;

    for (int i = tid; i < HH*GBM; i += 256) hT[i] = 0.f;
    __syncthreads();

    float rv[4][8], zv[4][8];

    for (int l = 0; l < LLN; l++) {
        for (int g = 0; g < 3; g++) {
            float acc[4][8];
#pragma unroll
            for (int i=0;i<4;i++)
#pragma unroll
                for (int j=0;j<8;j++) acc[i][j] = 0.f;

            for (int k0 = 0; k0 < HH; k0 += 16) {
#pragma unroll
                for (int it = 0; it < 4; it++) {
                    int idx = tid + it*256;
                    int r = idx >> 2, c = idx & 3;
                    float4 v = *(const float4*)(Whh + (size_t)(g*HH + r)*HH + k0 + c*4);
                    Ws[(c*4+0)*WSP + r] = v.x;
                    Ws[(c*4+1)*WSP + r] = v.y;
                    Ws[(c*4+2)*WSP + r] = v.z;
                    Ws[(c*4+3)*WSP + r] = v.w;
                }
                __syncthreads();
#pragma unroll
                for (int k = 0; k < 16; k++) {
                    float4 a  = *(const float4*)&hT[(k0+k)*GBM + tr*4];
                    float4 p  = *(const float4*)&Ws[k*WSP + tc*4];
                    float4 q  = *(const float4*)&Ws[k*WSP + 128 + tc*4];
                    float av[4] = {a.x,a.y,a.z,a.w};
                    float bv[8] = {p.x,p.y,p.z,p.w,q.x,q.y,q.z,q.w};
#pragma unroll
                    for (int i=0;i<4;i++)
#pragma unroll
                        for (int j=0;j<8;j++)
                            acc[i][j] = fmaf(av[i], bv[j], acc[i][j]);
                }
                __syncthreads();
            }

            // ---- gate epilogue ----
            float4 bh0 = *(const float4*)(bhh + g*HH + tc*4);
            float4 bh1 = *(const float4*)(bhh + g*HH + 128 + tc*4);
            float bb[8] = {bh0.x,bh0.y,bh0.z,bh0.w,bh1.x,bh1.y,bh1.z,bh1.w};

            if (g < 2) {
#pragma unroll
                for (int i=0;i<4;i++) {
                    const float* gp = g_gi + (size_t)(b0 + tr*4 + i)*GG + g*HH;
                    float4 gi0 = *(const float4*)(gp + tc*4);
                    float4 gi1 = *(const float4*)(gp + 128 + tc*4);
                    float gg[8] = {gi0.x,gi0.y,gi0.z,gi0.w,gi1.x,gi1.y,gi1.z,gi1.w};
#pragma unroll
                    for (int j=0;j<8;j++) {
                        float s = 1.f / (1.f + expf(-(gg[j] + acc[i][j] + bb[j])));
                        if (g == 0) rv[i][j] = s; else zv[i][j] = s;
                    }
                }
            } else {
#pragma unroll
                for (int i=0;i<4;i++) {
                    int m = tr*4 + i;
                    const float* gp = g_gi + (size_t)(b0 + m)*GG + 2*HH;
                    float4 gi0 = *(const float4*)(gp + tc*4);
                    float4 gi1 = *(const float4*)(gp + 128 + tc*4);
                    float gg[8] = {gi0.x,gi0.y,gi0.z,gi0.w,gi1.x,gi1.y,gi1.z,gi1.w};
                    float hn[8];
#pragma unroll
                    for (int j=0;j<8;j++) {
                        int col = (j < 4) ? (tc*4 + j) : (128 + tc*4 + (j - 4));
                        float n  = tanhf(gg[j] + rv[i][j]*(acc[i][j] + bb[j]));
                        float ho = hT[col*GBM + m];
                        hn[j] = (1.f - zv[i][j])*n + zv[i][j]*ho;
                        hT[col*GBM + m] = hn[j];   // own position only; safe after barrier
                    }
                    float* hp = g_hs + ((size_t)(b0+m)*LLN + l)*HH;
                    *(float4*)(hp + tc*4)       = make_float4(hn[0],hn[1],hn[2],hn[3]);
                    *(float4*)(hp + 128 + tc*4) = make_float4(hn[4],hn[5],hn[6],hn[7]);
                }
            }
        }
        // next pass's post-load __syncthreads orders hT writes before reads
    }
}

// ---------------- fused conv (y2) + head GEMM -------------------------------
// Block computes full y2 rows [128 x 256] into smem (BN2+PReLU on A-load,
// BN3+PReLU epilogue), then multiplies by W_mu^T [256 -> 32] locally.
// y2 never touches global memory.
#define ASP  132
#define WS2P 260
#define Y2P  260
#define WMP  261
#define CH_SMEM ((16*ASP + 16*WS2P + 128*Y2P + 32*WMP) * 4)

__global__ __launch_bounds__(512, 1) void convhead_kernel(
    const float* __restrict__ Wc,  const float* __restrict__ bc,
    const float* __restrict__ Wmu, const float* __restrict__ bmu,
    float* __restrict__ out)
{
    extern __shared__ float sm[];
    float* As  = sm;                       // [16][ASP]
    float* Ws  = As  + 16*ASP;             // [16][WS2P]
    float* y2s = Ws  + 16*WS2P;            // [128][Y2P]
    float* Wms = y2s + 128*Y2P;            // [32][WMP]

    const int tid = threadIdx.x;
    const int tr  = tid >> 5;              // 0..15 (TM=8)
    const int tc  = tid & 31;              // TN=8 split halves
    const size_t m0 = (size_t)blockIdx.x * 128;

    const float aA = g_al[1], aC = g_al[2];

    float acc[8][8];
#pragma unroll
    for (int i=0;i<8;i++)
#pragma unroll
        for (int j=0;j<8;j++) acc[i][j] = 0.f;

    for (int k0 = 0; k0 < HH; k0 += 16) {
        { // A tile: hs with BN2+PReLU transform, 1 float4/thread
            int r = tid >> 2, c = tid & 3;
            float4 v  = *(const float4*)(g_hs + (m0 + r)*HH + k0 + c*4);
            float4 s2 = *(const float4*)(g_s2 + k0 + c*4);
            float4 o2 = *(const float4*)(g_o2 + k0 + c*4);
            v.x = fmaf(v.x,s2.x,o2.x); v.x = v.x>=0.f ? v.x : aA*v.x;
            v.y = fmaf(v.y,s2.y,o2.y); v.y = v.y>=0.f ? v.y : aA*v.y;
            v.z = fmaf(v.z,s2.z,o2.z); v.z = v.z>=0.f ? v.z : aA*v.z;
            v.w = fmaf(v.w,s2.w,o2.w); v.w = v.w>=0.f ? v.w : aA*v.w;
            As[(c*4+0)*ASP + r] = v.x; As[(c*4+1)*ASP + r] = v.y;
            As[(c*4+2)*ASP + r] = v.z; As[(c*4+3)*ASP + r] = v.w;
        }
#pragma unroll
        for (int it = 0; it < 2; it++) {   // Wc tile
            int idx = tid + it*512;
            int r = idx >> 2, c = idx & 3;
            float4 v = *(const float4*)(Wc + (size_t)r*HH + k0 + c*4);
            Ws[(c*4+0)*WS2P + r] = v.x; Ws[(c*4+1)*WS2P + r] = v.y;
            Ws[(c*4+2)*WS2P + r] = v.z; Ws[(c*4+3)*WS2P + r] = v.w;
        }
        __syncthreads();
#pragma unroll
        for (int k = 0; k < 16; k++) {
            float4 a0 = *(const float4*)&As[k*ASP + tr*8];
            float4 a1 = *(const float4*)&As[k*ASP + tr*8 + 4];
            float4 p  = *(const float4*)&Ws[k*WS2P + tc*4];
            float4 q4 = *(const float4*)&Ws[k*WS2P + 128 + tc*4];
            float av[8] = {a0.x,a0.y,a0.z,a0.w,a1.x,a1.y,a1.z,a1.w};
            float bv[8] = {p.x,p.y,p.z,p.w,q4.x,q4.y,q4.z,q4.w};
#pragma unroll
            for (int i=0;i<8;i++)
#pragma unroll
                for (int j=0;j<8;j++)
                    acc[i][j] = fmaf(av[i], bv[j], acc[i][j]);
        }
        __syncthreads();
    }

    // epilogue: +bc, BN3+PReLU, into y2s
    {
        float4 bc0 = *(const float4*)(bc + tc*4);
        float4 bc1 = *(const float4*)(bc + 128 + tc*4);
        float4 s30 = *(const float4*)(g_s3 + tc*4);
        float4 s31 = *(const float4*)(g_s3 + 128 + tc*4);
        float4 o30 = *(const float4*)(g_o3 + tc*4);
        float4 o31 = *(const float4*)(g_o3 + 128 + tc*4);
        float bcv[8] = {bc0.x,bc0.y,bc0.z,bc0.w,bc1.x,bc1.y,bc1.z,bc1.w};
        float s3v[8] = {s30.x,s30.y,s30.z,s30.w,s31.x,s31.y,s31.z,s31.w};
        float o3v[8] = {o30.x,o30.y,o30.z,o30.w,o31.x,o31.y,o31.z,o31.w};
#pragma unroll
        for (int i=0;i<8;i++) {
            int m = tr*8 + i;
#pragma unroll
            for (int j=0;j<8;j++) {
                int col = (j < 4) ? (tc*4 + j) : (128 + tc*4 + (j - 4));
                float v = acc[i][j] + bcv[j];
                v = fmaf(v, s3v[j], o3v[j]);
                v = v >= 0.f ? v : aC*v;
                y2s[m*Y2P + col] = v;
            }
        }
    }
    // load W_mu into smem (scalar stores, padded rows)
#pragma unroll
    for (int it = 0; it < 4; it++) {
        int idx = tid + it*512;            // 0..2047 float4s
        int r = idx >> 6, c4 = idx & 63;
        float4 v = *(const float4*)(Wmu + (size_t)r*HH + c4*4);
        Wms[r*WMP + c4*4 + 0] = v.x; Wms[r*WMP + c4*4 + 1] = v.y;
        Wms[r*WMP + c4*4 + 2] = v.z; Wms[r*WMP + c4*4 + 3] = v.w;
    }
    __syncthreads();

    // head: out[m][o] = y2s[m][:] . Wmu[o][:] + bmu[o]
    {
        const int o  = tid & 31;
        const int mg = tid >> 5;           // 0..15
        float acc2[8];
#pragma unroll
        for (int i=0;i<8;i++) acc2[i] = 0.f;
        for (int k = 0; k < HH; k += 4) {
            float w0 = Wms[o*WMP + k + 0];
            float w1 = Wms[o*WMP + k + 1];
            float w2 = Wms[o*WMP + k + 2];
            float w3 = Wms[o*WMP + k + 3];
#pragma unroll
            for (int i=0;i<8;i++) {
                float4 y = *(const float4*)&y2s[(mg*8+i)*Y2P + k];
                acc2[i] = fmaf(y.x,w0, fmaf(y.y,w1, fmaf(y.z,w2, fmaf(y.w,w3, acc2[i]))));
            }
        }
        float bo = bmu[o];
#pragma unroll
        for (int i=0;i<8;i++)
            out[(m0 + mg*8 + i)*CC + o] = acc2[i] + bo;
    }
}

// ---------------- launch ----------------------------------------------------
extern "C" void kernel_launch(void* const* d_in, const int* in_sizes, int n_in,
                              void* d_out, int out_size)
{
    const float* A     = (const float*)d_in[0];
    const float* W_lin = (const float*)d_in[1];
    const float* b_lin = (const float*)d_in[2];
    const float* g1    = (const float*)d_in[3];
    const float* be1   = (const float*)d_in[4];
    const float* m1    = (const float*)d_in[5];
    const float* v1    = (const float*)d_in[6];
    const float* a1    = (const float*)d_in[7];
    const float* W_ih  = (const float*)d_in[8];
    const float* W_hh  = (const float*)d_in[9];
    const float* b_ih  = (const float*)d_in[10];
    const float* b_hh  = (const float*)d_in[11];
    const float* g2    = (const float*)d_in[12];
    const float* be2   = (const float*)d_in[13];
    const float* m2    = (const float*)d_in[14];
    const float* v2    = (const float*)d_in[15];
    const float* a2    = (const float*)d_in[16];
    const float* Wc    = (const float*)d_in[17];
    const float* bc    = (const float*)d_in[18];
    const float* g3    = (const float*)d_in[19];
    const float* be3   = (const float*)d_in[20];
    const float* m3    = (const float*)d_in[21];
    const float* v3    = (const float*)d_in[22];
    const float* a3    = (const float*)d_in[23];
    const float* W_mu  = (const float*)d_in[24];
    const float* b_mu  = (const float*)d_in[25];
    float* out = (float*)d_out;

    float *px, *pgi;
    cudaGetSymbolAddress((void**)&px,  g_x);
    cudaGetSymbolAddress((void**)&pgi, g_gi);

    static bool attr_done = false;
    if (!attr_done) {
        cudaFuncSetAttribute(gru_fused_kernel,
                             cudaFuncAttributeMaxDynamicSharedMemorySize, GRU_SMEM);
        cudaFuncSetAttribute(convhead_kernel,
                             cudaFuncAttributeMaxDynamicSharedMemorySize, CH_SMEM);
        attr_done = true;
    }

    prep_kernel<<<1, 256>>>(g1, be1, m1, v1, a1, g2, be2, m2, v2, a2, g3, be3, m3, v3, a3);

    // x = PReLU(BN1(A @ W_lin^T + b_lin)) : [8192,256], K=640
    gemm_kernel<128,128,16,8,8,1><<<dim3(HH/128, BB/128), 256>>>(A, W_lin, b_lin, px, BB, HH, FF);

    // gi = x @ W_ih^T + b_ih : [8192,768], K=256
    gemm_kernel<128,128,16,8,8,0><<<dim3(GG/128, BB/128), 256>>>(px, W_ih, b_ih, pgi, BB, GG, HH);

    // fused 20-step GRU (one launch)
    gru_fused_kernel<<<BB/GBM, 256, GRU_SMEM>>>(W_hh, b_hh);

    // fused conv + head, writes d_out directly
    convhead_kernel<<<BLM/128, 512, CH_SMEM>>>(Wc, bc, W_mu, b_mu, out);
}

// round 4
// speedup vs baseline: 1.2292x; 1.2292x over previous
#include <cuda_runtime.h>
#include <math.h>

#define EE 64
#define SSZ 128
#define FF 640
#define HH 256
#define GG 768          // 3*H
#define LLN 20
#define CC 32
#define BB (EE*SSZ)     // 8192
#define BLM (BB*LLN)    // 163840
#define EPSV 1e-5f

// ---------------- scratch (static __device__, no allocation) ----------------
__device__ float g_x [BB*HH];       // 8 MB
__device__ float g_gi[BB*GG];       // 24 MB
__device__ float g_h [BB*HH];       // 8 MB
__device__ float g_gh[BB*GG];       // 24 MB
__device__ float g_hs[BLM*HH];      // 160 MB, layout [b][l][h]
__device__ float g_y2[BLM*HH];      // 160 MB
__device__ float g_s1[HH], g_o1[HH];
__device__ float g_s2[HH], g_o2[HH];
__device__ float g_s3[HH], g_o3[HH];
__device__ float g_al[3];

// ---------------- prep ------------------------------------------------------
__global__ void prep_kernel(const float* g1,const float* b1,const float* m1,const float* v1,const float* a1,
                            const float* g2,const float* b2,const float* m2,const float* v2,const float* a2,
                            const float* g3,const float* b3,const float* m3,const float* v3,const float* a3)
{
    int i = threadIdx.x;
    float s;
    s = g1[i] / sqrtf(v1[i] + EPSV); g_s1[i] = s; g_o1[i] = b1[i] - m1[i]*s;
    s = g2[i] / sqrtf(v2[i] + EPSV); g_s2[i] = s; g_o2[i] = b2[i] - m2[i]*s;
    s = g3[i] / sqrtf(v3[i] + EPSV); g_s3[i] = s; g_o3[i] = b3[i] - m3[i]*s;
    if (i == 0) { g_al[0] = a1[0]; g_al[1] = a2[0]; g_al[2] = a3[0]; }
}

__global__ void zero_h_kernel()
{
    int i = blockIdx.x * blockDim.x + threadIdx.x;
    ((float4*)g_h)[i] = make_float4(0.f, 0.f, 0.f, 0.f);
}

// ---------------- double-buffered tiled fp32 GEMM ---------------------------
// C = epi(A @ W^T + bias).  A:[M,K], W:[N,K] row-major.  BM=128, BK=8 fixed by
// the load mapping (exactly 1 float4 per thread per tile for A).
// MODE 0: bias only
// MODE 1: bias, then BN1+PReLU
// MODE 2: BN2+PReLU transform on A load; epilogue bias + BN3+PReLU
template<int BM,int BN,int BK,int TM,int TN,int MODE>
__global__ __launch_bounds__(256, 2) void gemm_db(
    const float* __restrict__ A, const float* __restrict__ W,
    const float* __restrict__ bias, float* __restrict__ Cst,
    int M, int N, int K)
{
    __shared__ float As[2][BK][BM+4];
    __shared__ float Ws[2][BK][BN+4];

    const int tid = threadIdx.x;
    const int m0  = blockIdx.y * BM;
    const int n0  = blockIdx.x * BN;
    constexpr int CT  = BN / TN;
    const int tr = tid / CT;
    const int tc = tid % CT;
    constexpr int TNh = TN / 2;

    constexpr int KF4 = BK / 4;            // 2
    constexpr int NW4 = BN * KF4;
    const int ar = tid / KF4, ac = tid % KF4;       // A: 1 float4/thread
    const bool wok = (NW4 >= 256) || (tid < NW4);   // W: guarded for BN<128
    const int wr = tid / KF4, wc = tid % KF4;

    const float aA = (MODE == 2) ? g_al[1] : 0.f;

    const float* Aptr = A + (size_t)(m0 + ar) * K + ac * 4;
    const float* Wptr = W + (size_t)(n0 + wr) * K + wc * 4;

    float acc[TM][TN];
#pragma unroll
    for (int i = 0; i < TM; i++)
#pragma unroll
        for (int j = 0; j < TN; j++) acc[i][j] = 0.f;

    // ---- load tile 0 ----
    float4 av = *(const float4*)Aptr;
    if (MODE == 2) {
        float4 s2 = *(const float4*)(g_s2 + ac*4);
        float4 o2 = *(const float4*)(g_o2 + ac*4);
        av.x = fmaf(av.x,s2.x,o2.x); av.x = av.x>=0.f ? av.x : aA*av.x;
        av.y = fmaf(av.y,s2.y,o2.y); av.y = av.y>=0.f ? av.y : aA*av.y;
        av.z = fmaf(av.z,s2.z,o2.z); av.z = av.z>=0.f ? av.z : aA*av.z;
        av.w = fmaf(av.w,s2.w,o2.w); av.w = av.w>=0.f ? av.w : aA*av.w;
    }
    float4 wv = wok ? *(const float4*)Wptr : make_float4(0,0,0,0);

    As[0][ac*4+0][ar] = av.x; As[0][ac*4+1][ar] = av.y;
    As[0][ac*4+2][ar] = av.z; As[0][ac*4+3][ar] = av.w;
    if (wok) {
        Ws[0][wc*4+0][wr] = wv.x; Ws[0][wc*4+1][wr] = wv.y;
        Ws[0][wc*4+2][wr] = wv.z; Ws[0][wc*4+3][wr] = wv.w;
    }
    __syncthreads();

    const int T = K / BK;
    int buf = 0;

    for (int t = 0; t < T; t++) {
        // ---- prefetch next tile into registers (overlaps with compute) ----
        float4 aP, wP;
        if (t + 1 < T) {
            aP = *(const float4*)(Aptr + (t+1)*BK);
            if (MODE == 2) {
                int kk = (t+1)*BK + ac*4;
                float4 s2 = *(const float4*)(g_s2 + kk);
                float4 o2 = *(const float4*)(g_o2 + kk);
                aP.x = fmaf(aP.x,s2.x,o2.x); aP.x = aP.x>=0.f ? aP.x : aA*aP.x;
                aP.y = fmaf(aP.y,s2.y,o2.y); aP.y = aP.y>=0.f ? aP.y : aA*aP.y;
                aP.z = fmaf(aP.z,s2.z,o2.z); aP.z = aP.z>=0.f ? aP.z : aA*aP.z;
                aP.w = fmaf(aP.w,s2.w,o2.w); aP.w = aP.w>=0.f ? aP.w : aA*aP.w;
            }
            if (wok) wP = *(const float4*)(Wptr + (t+1)*BK);
        }

        // ---- compute with register-fragment double buffering ----
        float ra[2][TM], rb[2][TN];
        {   // frag k=0
            float4 a0 = *(const float4*)&As[buf][0][tr*TM];
            float4 a1 = *(const float4*)&As[buf][0][tr*TM+4];
            ra[0][0]=a0.x; ra[0][1]=a0.y; ra[0][2]=a0.z; ra[0][3]=a0.w;
            ra[0][4]=a1.x; ra[0][5]=a1.y; ra[0][6]=a1.z; ra[0][7]=a1.w;
            if constexpr (TN == 8) {
                float4 b0 = *(const float4*)&Ws[buf][0][tc*4];
                float4 b1 = *(const float4*)&Ws[buf][0][BN/2 + tc*4];
                rb[0][0]=b0.x; rb[0][1]=b0.y; rb[0][2]=b0.z; rb[0][3]=b0.w;
                rb[0][4]=b1.x; rb[0][5]=b1.y; rb[0][6]=b1.z; rb[0][7]=b1.w;
            } else {
                rb[0][0] = Ws[buf][0][tc];
                rb[0][1] = Ws[buf][0][BN/2 + tc];
            }
        }
#pragma unroll
        for (int k = 0; k < BK; k++) {
            const int cur = k & 1, nxt = cur ^ 1;
            if (k + 1 < BK) {
                float4 a0 = *(const float4*)&As[buf][k+1][tr*TM];
                float4 a1 = *(const float4*)&As[buf][k+1][tr*TM+4];
                ra[nxt][0]=a0.x; ra[nxt][1]=a0.y; ra[nxt][2]=a0.z; ra[nxt][3]=a0.w;
                ra[nxt][4]=a1.x; ra[nxt][5]=a1.y; ra[nxt][6]=a1.z; ra[nxt][7]=a1.w;
                if constexpr (TN == 8) {
                    float4 b0 = *(const float4*)&Ws[buf][k+1][tc*4];
                    float4 b1 = *(const float4*)&Ws[buf][k+1][BN/2 + tc*4];
                    rb[nxt][0]=b0.x; rb[nxt][1]=b0.y; rb[nxt][2]=b0.z; rb[nxt][3]=b0.w;
                    rb[nxt][4]=b1.x; rb[nxt][5]=b1.y; rb[nxt][6]=b1.z; rb[nxt][7]=b1.w;
                } else {
                    rb[nxt][0] = Ws[buf][k+1][tc];
                    rb[nxt][1] = Ws[buf][k+1][BN/2 + tc];
                }
            }
#pragma unroll
            for (int i = 0; i < TM; i++)
#pragma unroll
                for (int j = 0; j < TN; j++)
                    acc[i][j] = fmaf(ra[cur][i], rb[cur][j], acc[i][j]);
        }

        // ---- store prefetched tile, flip ----
        if (t + 1 < T) {
            const int nb = buf ^ 1;
            As[nb][ac*4+0][ar] = aP.x; As[nb][ac*4+1][ar] = aP.y;
            As[nb][ac*4+2][ar] = aP.z; As[nb][ac*4+3][ar] = aP.w;
            if (wok) {
                Ws[nb][wc*4+0][wr] = wP.x; Ws[nb][wc*4+1][wr] = wP.y;
                Ws[nb][wc*4+2][wr] = wP.z; Ws[nb][wc*4+3][wr] = wP.w;
            }
            __syncthreads();
            buf = nb;
        }
    }

    // ---- epilogue ----
#pragma unroll
    for (int j = 0; j < TN; j++) {
        int n = n0 + ((j < TNh) ? (tc*TNh + j) : (BN/2 + tc*TNh + (j - TNh)));
        float bsv = bias[n];
        float sc = 1.f, off = 0.f, al = 0.f;
        if (MODE == 1) { sc = g_s1[n]; off = g_o1[n]; al = g_al[0]; }
        if (MODE == 2) { sc = g_s3[n]; off = g_o3[n]; al = g_al[2]; }
#pragma unroll
        for (int i = 0; i < TM; i++) {
            int m = m0 + tr*TM + i;
            float v = acc[i][j] + bsv;
            if (MODE >= 1) { v = v*sc + off; v = v >= 0.f ? v : al*v; }
            Cst[(size_t)m * N + n] = v;
        }
    }
}

// ---------------- GRU gate elementwise step ---------------------------------
__device__ __forceinline__ float sigf(float x) { return 1.f / (1.f + expf(-x)); }

__global__ void gate_kernel(int l)
{
    int idx = blockIdx.x * blockDim.x + threadIdx.x;   // over BB*HH/4
    int j4 = idx % (HH/4);
    int b  = idx / (HH/4);
    int base = b * (GG/4);

    float4 gir = ((const float4*)g_gi)[base            + j4];
    float4 giz = ((const float4*)g_gi)[base +   HH/4   + j4];
    float4 gin = ((const float4*)g_gi)[base + 2*(HH/4) + j4];
    float4 ghr = ((const float4*)g_gh)[base            + j4];
    float4 ghz = ((const float4*)g_gh)[base +   HH/4   + j4];
    float4 ghn = ((const float4*)g_gh)[base + 2*(HH/4) + j4];
    float4 h   = ((const float4*)g_h )[b*(HH/4) + j4];

    float r, z, n;
    r = sigf(gir.x + ghr.x); z = sigf(giz.x + ghz.x);
    n = tanhf(gin.x + r*ghn.x); h.x = (1.f - z)*n + z*h.x;
    r = sigf(gir.y + ghr.y); z = sigf(giz.y + ghz.y);
    n = tanhf(gin.y + r*ghn.y); h.y = (1.f - z)*n + z*h.y;
    r = sigf(gir.z + ghr.z); z = sigf(giz.z + ghz.z);
    n = tanhf(gin.z + r*ghn.z); h.z = (1.f - z)*n + z*h.z;
    r = sigf(gir.w + ghr.w); z = sigf(giz.w + ghz.w);
    n = tanhf(gin.w + r*ghn.w); h.w = (1.f - z)*n + z*h.w;

    ((float4*)g_h)[b*(HH/4) + j4] = h;
    ((float4*)g_hs)[((size_t)b*LLN + l)*(HH/4) + j4] = h;
}

// ---------------- launch ----------------------------------------------------
extern "C" void kernel_launch(void* const* d_in, const int* in_sizes, int n_in,
                              void* d_out, int out_size)
{
    const float* A     = (const float*)d_in[0];
    const float* W_lin = (const float*)d_in[1];
    const float* b_lin = (const float*)d_in[2];
    const float* g1    = (const float*)d_in[3];
    const float* be1   = (const float*)d_in[4];
    const float* m1    = (const float*)d_in[5];
    const float* v1    = (const float*)d_in[6];
    const float* a1    = (const float*)d_in[7];
    const float* W_ih  = (const float*)d_in[8];
    const float* W_hh  = (const float*)d_in[9];
    const float* b_ih  = (const float*)d_in[10];
    const float* b_hh  = (const float*)d_in[11];
    const float* g2    = (const float*)d_in[12];
    const float* be2   = (const float*)d_in[13];
    const float* m2    = (const float*)d_in[14];
    const float* v2    = (const float*)d_in[15];
    const float* a2    = (const float*)d_in[16];
    const float* Wc    = (const float*)d_in[17];
    const float* bc    = (const float*)d_in[18];
    const float* g3    = (const float*)d_in[19];
    const float* be3   = (const float*)d_in[20];
    const float* m3    = (const float*)d_in[21];
    const float* v3    = (const float*)d_in[22];
    const float* a3    = (const float*)d_in[23];
    const float* W_mu  = (const float*)d_in[24];
    const float* b_mu  = (const float*)d_in[25];
    float* out = (float*)d_out;

    float *px, *pgi, *ph, *pgh, *phs, *py2;
    cudaGetSymbolAddress((void**)&px,  g_x);
    cudaGetSymbolAddress((void**)&pgi, g_gi);
    cudaGetSymbolAddress((void**)&ph,  g_h);
    cudaGetSymbolAddress((void**)&pgh, g_gh);
    cudaGetSymbolAddress((void**)&phs, g_hs);
    cudaGetSymbolAddress((void**)&py2, g_y2);

    prep_kernel<<<1, 256>>>(g1, be1, m1, v1, a1, g2, be2, m2, v2, a2, g3, be3, m3, v3, a3);
    zero_h_kernel<<<(BB*HH/4)/256, 256>>>();

    // x = PReLU(BN1(A @ W_lin^T + b_lin)) : [8192,256], K=640
    gemm_db<128,128,8,8,8,1><<<dim3(HH/128, BB/128), 256>>>(A, W_lin, b_lin, px, BB, HH, FF);

    // gi = x @ W_ih^T + b_ih : [8192,768], K=256
    gemm_db<128,128,8,8,8,0><<<dim3(GG/128, BB/128), 256>>>(px, W_ih, b_ih, pgi, BB, GG, HH);

    // GRU recurrence
    for (int l = 0; l < LLN; l++) {
        gemm_db<128,128,8,8,8,0><<<dim3(GG/128, BB/128), 256>>>(ph, W_hh, b_hh, pgh, BB, GG, HH);
        gate_kernel<<<(BB*HH/4)/256, 256>>>(l);
    }

    // y2 = PReLU(BN3(PReLU(BN2(hs)) @ Wc^T + bc)) : [163840,256], K=256
    gemm_db<128,128,8,8,8,2><<<dim3(HH/128, BLM/128), 256>>>(phs, Wc, bc, py2, BLM, HH, HH);

    // pred = y2 @ W_mu^T + b_mu : [163840,32]
    gemm_db<128,32,8,8,2,0><<<dim3(1, BLM/128), 256>>>(py2, W_mu, b_mu, out, BLM, CC, HH);
}

// round 6
// speedup vs baseline: 2.2460x; 1.8272x over previous
#include <cuda_runtime.h>
#include <math.h>
#include <stdint.h>

#define EE 64
#define SSZ 128
#define FF 640
#define HH 256
#define GG 768          // 3*H
#define LLN 20
#define CC 32
#define BB (EE*SSZ)     // 8192
#define BLM (BB*LLN)    // 163840
#define EPSV 1e-5f

// ---------------- scratch (static __device__, no allocation) ----------------
__device__ float g_x [BB*HH];       // 8 MB
__device__ float g_gi[BB*GG];       // 24 MB
__device__ float g_h [BB*HH];       // 8 MB
__device__ float g_gh[BB*GG];       // 24 MB
__device__ float g_hs[BLM*HH];      // 160 MB, layout [b][l][h]
__device__ float g_y2[BLM*HH];      // 160 MB
__device__ float g_s1[HH], g_o1[HH];
__device__ float g_s2[HH], g_o2[HH];
__device__ float g_s3[HH], g_o3[HH];
__device__ float g_al[3];

// ---------------- helpers ----------------------------------------------------
__device__ __forceinline__ uint32_t f2tf(float x) {
    uint32_t r;
    asm("cvt.rna.tf32.f32 %0, %1;" : "=r"(r) : "f"(x));
    return r;
}
__device__ __forceinline__ void mma8(float* c, const uint32_t* a, const uint32_t* b) {
    asm volatile("mma.sync.aligned.m16n8k8.row.col.f32.tf32.tf32.f32 "
        "{%0,%1,%2,%3},{%4,%5,%6,%7},{%8,%9},{%0,%1,%2,%3};"
        : "+f"(c[0]), "+f"(c[1]), "+f"(c[2]), "+f"(c[3])
        : "r"(a[0]), "r"(a[1]), "r"(a[2]), "r"(a[3]), "r"(b[0]), "r"(b[1]));
}

// ---------------- prep ------------------------------------------------------
__global__ void prep_kernel(const float* g1,const float* b1,const float* m1,const float* v1,const float* a1,
                            const float* g2,const float* b2,const float* m2,const float* v2,const float* a2,
                            const float* g3,const float* b3,const float* m3,const float* v3,const float* a3)
{
    int i = threadIdx.x;
    float s;
    s = g1[i] / sqrtf(v1[i] + EPSV); g_s1[i] = s; g_o1[i] = b1[i] - m1[i]*s;
    s = g2[i] / sqrtf(v2[i] + EPSV); g_s2[i] = s; g_o2[i] = b2[i] - m2[i]*s;
    s = g3[i] / sqrtf(v3[i] + EPSV); g_s3[i] = s; g_o3[i] = b3[i] - m3[i]*s;
    if (i == 0) { g_al[0] = a1[0]; g_al[1] = a2[0]; g_al[2] = a3[0]; }
}

__global__ void zero_h_kernel()
{
    int i = blockIdx.x * blockDim.x + threadIdx.x;
    ((float4*)g_h)[i] = make_float4(0.f, 0.f, 0.f, 0.f);
}

// ---------------- tf32 mma.sync GEMM ----------------------------------------
// C = epi(A @ W^T + bias). A:[M,K], W:[N,K] row-major.
// Block tile BM x BN, BK=16, 256 threads = 8 warps laid out WM x WN.
// Warp tile (BM/WM) x (BN/WN) built from m16n8k8 tf32 mma fragments.
// Smem k-major [k][m]+pad4 -> conflict-free scalar fragment loads.
// MODE 0: bias. MODE 1: bias+BN1+PReLU. MODE 2: BN2+PReLU on A load,
// bias+BN3+PReLU epilogue.
template<int BM,int BN,int BK,int WM,int WN,int MODE>
__global__ __launch_bounds__(256, 2) void mma_gemm(
    const float* __restrict__ A, const float* __restrict__ W,
    const float* __restrict__ bias, float* __restrict__ Cst,
    int M, int N, int K)
{
    constexpr int BMP = BM + 4, BNP = BN + 4;
    __shared__ uint32_t As[2][BK][BMP];
    __shared__ uint32_t Ws[2][BK][BNP];

    const int tid  = threadIdx.x;
    const int wid  = tid >> 5;
    const int lane = tid & 31;
    const int wm   = wid % WM;
    const int wn   = wid / WM;
    constexpr int WTM = BM / WM;
    constexpr int WTN = BN / WN;
    constexpr int MT  = WTM / 16;
    constexpr int NT  = WTN / 8;

    const int m0 = blockIdx.y * BM;
    const int n0 = blockIdx.x * BN;

    constexpr int KF4  = BK / 4;                 // 4
    constexpr int NF4A = BM * KF4;               // float4s per A tile
    constexpr int NF4W = BN * KF4;
    constexpr int AIT  = NF4A / 256;             // 2 for BM=128
    constexpr int WIT  = (NF4W + 255) / 256;

    const float aA = (MODE == 2) ? g_al[1] : 0.f;
    const int qr = lane >> 2, qc = lane & 3;     // groupID, threadID_in_group

    float acc[MT][NT][4];
#pragma unroll
    for (int i = 0; i < MT; i++)
#pragma unroll
        for (int j = 0; j < NT; j++)
#pragma unroll
            for (int q = 0; q < 4; q++) acc[i][j][q] = 0.f;

    const int T = K / BK;

    // ---- tile load helpers (as lambdas via macros) ----
#define LOAD_A_F4(dst, t, it) { \
        int idx = tid + (it)*256; \
        int r = idx >> 2, c = idx & 3; \
        float4 v = *(const float4*)(A + (size_t)(m0 + r) * K + (t)*BK + c*4); \
        if (MODE == 2) { \
            float4 s2 = *(const float4*)(g_s2 + (t)*BK + c*4); \
            float4 o2 = *(const float4*)(g_o2 + (t)*BK + c*4); \
            v.x = fmaf(v.x,s2.x,o2.x); v.x = v.x>=0.f ? v.x : aA*v.x; \
            v.y = fmaf(v.y,s2.y,o2.y); v.y = v.y>=0.f ? v.y : aA*v.y; \
            v.z = fmaf(v.z,s2.z,o2.z); v.z = v.z>=0.f ? v.z : aA*v.z; \
            v.w = fmaf(v.w,s2.w,o2.w); v.w = v.w>=0.f ? v.w : aA*v.w; \
        } \
        dst = v; }
#define STORE_A_F4(buf, v, it) { \
        int idx = tid + (it)*256; \
        int r = idx >> 2, c = idx & 3; \
        As[buf][c*4+0][r] = f2tf(v.x); As[buf][c*4+1][r] = f2tf(v.y); \
        As[buf][c*4+2][r] = f2tf(v.z); As[buf][c*4+3][r] = f2tf(v.w); }
#define LOAD_W_F4(dst, t, it, ok) { \
        int idx = tid + (it)*256; \
        if (ok) { \
            int r = idx >> 2, c = idx & 3; \
            dst = *(const float4*)(W + (size_t)(n0 + r) * K + (t)*BK + c*4); \
        } }
#define STORE_W_F4(buf, v, it, ok) { \
        int idx = tid + (it)*256; \
        if (ok) { \
            int r = idx >> 2, c = idx & 3; \
            Ws[buf][c*4+0][r] = f2tf(v.x); Ws[buf][c*4+1][r] = f2tf(v.y); \
            Ws[buf][c*4+2][r] = f2tf(v.z); Ws[buf][c*4+3][r] = f2tf(v.w); } }

    // ---- load tile 0 ----
    {
        float4 a[AIT], w[WIT];
#pragma unroll
        for (int it = 0; it < AIT; it++) LOAD_A_F4(a[it], 0, it);
#pragma unroll
        for (int it = 0; it < WIT; it++) {
            bool ok = (NF4W >= 256*(it+1)) || (tid + it*256 < NF4W);
            LOAD_W_F4(w[it], 0, it, ok);
        }
#pragma unroll
        for (int it = 0; it < AIT; it++) STORE_A_F4(0, a[it], it);
#pragma unroll
        for (int it = 0; it < WIT; it++) {
            bool ok = (NF4W >= 256*(it+1)) || (tid + it*256 < NF4W);
            STORE_W_F4(0, w[it], it, ok);
        }
    }
    __syncthreads();

    int buf = 0;
    for (int t = 0; t < T; t++) {
        // prefetch next tile into registers
        float4 aP[AIT], wP[WIT];
        if (t + 1 < T) {
#pragma unroll
            for (int it = 0; it < AIT; it++) LOAD_A_F4(aP[it], t+1, it);
#pragma unroll
            for (int it = 0; it < WIT; it++) {
                bool ok = (NF4W >= 256*(it+1)) || (tid + it*256 < NF4W);
                LOAD_W_F4(wP[it], t+1, it, ok);
            }
        }

        // compute: BK/8 k-steps of m16n8k8
#pragma unroll
        for (int ks = 0; ks < BK/8; ks++) {
            const int kb = ks * 8;
            uint32_t af[MT][4], bf[NT][2];
#pragma unroll
            for (int mt = 0; mt < MT; mt++) {
                const int m = wm*WTM + mt*16 + qr;
                af[mt][0] = As[buf][kb + qc    ][m];
                af[mt][1] = As[buf][kb + qc    ][m + 8];
                af[mt][2] = As[buf][kb + qc + 4][m];
                af[mt][3] = As[buf][kb + qc + 4][m + 8];
            }
#pragma unroll
            for (int nt = 0; nt < NT; nt++) {
                const int n = wn*WTN + nt*8 + qr;
                bf[nt][0] = Ws[buf][kb + qc    ][n];
                bf[nt][1] = Ws[buf][kb + qc + 4][n];
            }
#pragma unroll
            for (int mt = 0; mt < MT; mt++)
#pragma unroll
                for (int nt = 0; nt < NT; nt++)
                    mma8(acc[mt][nt], af[mt], bf[nt]);
        }

        if (t + 1 < T) {
            const int nb = buf ^ 1;
#pragma unroll
            for (int it = 0; it < AIT; it++) STORE_A_F4(nb, aP[it], it);
#pragma unroll
            for (int it = 0; it < WIT; it++) {
                bool ok = (NF4W >= 256*(it+1)) || (tid + it*256 < NF4W);
                STORE_W_F4(nb, wP[it], it, ok);
            }
            __syncthreads();
            buf = nb;
        }
    }

    // ---- epilogue ----
#pragma unroll
    for (int mt = 0; mt < MT; mt++) {
#pragma unroll
        for (int nt = 0; nt < NT; nt++) {
            const int row = m0 + wm*WTM + mt*16 + qr;
            const int col = n0 + wn*WTN + nt*8 + 2*qc;
            float2 bv = *(const float2*)(bias + col);
            float x0 = acc[mt][nt][0] + bv.x;
            float x1 = acc[mt][nt][1] + bv.y;
            float x2 = acc[mt][nt][2] + bv.x;
            float x3 = acc[mt][nt][3] + bv.y;
            if (MODE == 1 || MODE == 2) {
                const float* sp = (MODE == 1) ? g_s1 : g_s3;
                const float* op = (MODE == 1) ? g_o1 : g_o3;
                const float al  = (MODE == 1) ? g_al[0] : g_al[2];
                float2 sv = *(const float2*)(sp + col);
                float2 ov = *(const float2*)(op + col);
                x0 = fmaf(x0, sv.x, ov.x); x0 = x0>=0.f ? x0 : al*x0;
                x1 = fmaf(x1, sv.y, ov.y); x1 = x1>=0.f ? x1 : al*x1;
                x2 = fmaf(x2, sv.x, ov.x); x2 = x2>=0.f ? x2 : al*x2;
                x3 = fmaf(x3, sv.y, ov.y); x3 = x3>=0.f ? x3 : al*x3;
            }
            *(float2*)(Cst + (size_t)row * N + col)       = make_float2(x0, x1);
            *(float2*)(Cst + (size_t)(row + 8) * N + col) = make_float2(x2, x3);
        }
    }
#undef LOAD_A_F4
#undef STORE_A_F4
#undef LOAD_W_F4
#undef STORE_W_F4
}

// ---------------- GRU gate elementwise step ---------------------------------
__device__ __forceinline__ float sigf(float x) { return 1.f / (1.f + expf(-x)); }

__global__ void gate_kernel(int l)
{
    int idx = blockIdx.x * blockDim.x + threadIdx.x;   // over BB*HH/4
    int j4 = idx % (HH/4);
    int b  = idx / (HH/4);
    int base = b * (GG/4);

    float4 gir = ((const float4*)g_gi)[base            + j4];
    float4 giz = ((const float4*)g_gi)[base +   HH/4   + j4];
    float4 gin = ((const float4*)g_gi)[base + 2*(HH/4) + j4];
    float4 ghr = ((const float4*)g_gh)[base            + j4];
    float4 ghz = ((const float4*)g_gh)[base +   HH/4   + j4];
    float4 ghn = ((const float4*)g_gh)[base + 2*(HH/4) + j4];
    float4 h   = ((const float4*)g_h )[b*(HH/4) + j4];

    float r, z, n;
    r = sigf(gir.x + ghr.x); z = sigf(giz.x + ghz.x);
    n = tanhf(gin.x + r*ghn.x); h.x = (1.f - z)*n + z*h.x;
    r = sigf(gir.y + ghr.y); z = sigf(giz.y + ghz.y);
    n = tanhf(gin.y + r*ghn.y); h.y = (1.f - z)*n + z*h.y;
    r = sigf(gir.z + ghr.z); z = sigf(giz.z + ghz.z);
    n = tanhf(gin.z + r*ghn.z); h.z = (1.f - z)*n + z*h.z;
    r = sigf(gir.w + ghr.w); z = sigf(giz.w + ghz.w);
    n = tanhf(gin.w + r*ghn.w); h.w = (1.f - z)*n + z*h.w;

    ((float4*)g_h)[b*(HH/4) + j4] = h;
    ((float4*)g_hs)[((size_t)b*LLN + l)*(HH/4) + j4] = h;
}

// ---------------- launch ----------------------------------------------------
extern "C" void kernel_launch(void* const* d_in, const int* in_sizes, int n_in,
                              void* d_out, int out_size)
{
    const float* A     = (const float*)d_in[0];
    const float* W_lin = (const float*)d_in[1];
    const float* b_lin = (const float*)d_in[2];
    const float* g1    = (const float*)d_in[3];
    const float* be1   = (const float*)d_in[4];
    const float* m1    = (const float*)d_in[5];
    const float* v1    = (const float*)d_in[6];
    const float* a1    = (const float*)d_in[7];
    const float* W_ih  = (const float*)d_in[8];
    const float* W_hh  = (const float*)d_in[9];
    const float* b_ih  = (const float*)d_in[10];
    const float* b_hh  = (const float*)d_in[11];
    const float* g2    = (const float*)d_in[12];
    const float* be2   = (const float*)d_in[13];
    const float* m2    = (const float*)d_in[14];
    const float* v2    = (const float*)d_in[15];
    const float* a2    = (const float*)d_in[16];
    const float* Wc    = (const float*)d_in[17];
    const float* bc    = (const float*)d_in[18];
    const float* g3    = (const float*)d_in[19];
    const float* be3   = (const float*)d_in[20];
    const float* m3    = (const float*)d_in[21];
    const float* v3    = (const float*)d_in[22];
    const float* a3    = (const float*)d_in[23];
    const float* W_mu  = (const float*)d_in[24];
    const float* b_mu  = (const float*)d_in[25];
    float* out = (float*)d_out;

    float *px, *pgi, *ph, *pgh, *phs, *py2;
    cudaGetSymbolAddress((void**)&px,  g_x);
    cudaGetSymbolAddress((void**)&pgi, g_gi);
    cudaGetSymbolAddress((void**)&ph,  g_h);
    cudaGetSymbolAddress((void**)&pgh, g_gh);
    cudaGetSymbolAddress((void**)&phs, g_hs);
    cudaGetSymbolAddress((void**)&py2, g_y2);

    prep_kernel<<<1, 256>>>(g1, be1, m1, v1, a1, g2, be2, m2, v2, a2, g3, be3, m3, v3, a3);
    zero_h_kernel<<<(BB*HH/4)/256, 256>>>();

    // x = PReLU(BN1(A @ W_lin^T + b_lin)) : [8192,256], K=640
    mma_gemm<128,128,16,4,2,1><<<dim3(HH/128, BB/128), 256>>>(A, W_lin, b_lin, px, BB, HH, FF);

    // gi = x @ W_ih^T + b_ih : [8192,768], K=256
    mma_gemm<128,128,16,4,2,0><<<dim3(GG/128, BB/128), 256>>>(px, W_ih, b_ih, pgi, BB, GG, HH);

    // GRU recurrence
    for (int l = 0; l < LLN; l++) {
        mma_gemm<128,128,16,4,2,0><<<dim3(GG/128, BB/128), 256>>>(ph, W_hh, b_hh, pgh, BB, GG, HH);
        gate_kernel<<<(BB*HH/4)/256, 256>>>(l);
    }

    // y2 = PReLU(BN3(PReLU(BN2(hs)) @ Wc^T + bc)) : [163840,256], K=256
    mma_gemm<128,128,16,4,2,2><<<dim3(HH/128, BLM/128), 256>>>(phs, Wc, bc, py2, BLM, HH, HH);

    // pred = y2 @ W_mu^T + b_mu : [163840,32]
    mma_gemm<128,32,16,8,1,0><<<dim3(1, BLM/128), 256>>>(py2, W_mu, b_mu, out, BLM, CC, HH);
}